// round 7
// baseline (speedup 1.0000x reference)
#include <cuda_runtime.h>
#include <stdint.h>

// Haar DWT level-1 on x: (B=32, L=4096, F=512) fp32.
// out[b, p, f]      = (x[b,2p,f] + x[b,2p+1,f]) / sqrt2   (p in [0,2048))
// out[b, 2048+p, f] = (x[b,2p,f] - x[b,2p+1,f]) / sqrt2
//
// Best-known config (R3) micro-tuned: lane = f4 stride-1 coalesced, MLP=4
// via two distant pairs, plain ld/st, 32-bit index math, 512-thread blocks.

#define B 32
#define L 4096
#define F 512
#define HALF_L (L / 2)
#define F4 (F / 4)                        // 128 float4 per row
#define PQ (HALF_L / 2)                   // 1024 pair-indices
#define TOTAL_T (B * PQ * F4)             // 4,194,304 threads
#define ROW F4
#define DOFF (HALF_L * F4)                // detail block offset (float4 elems)

__global__ __launch_bounds__(512) void haar_dwt_kernel(
    const float4* __restrict__ x, float4* __restrict__ out)
{
    unsigned t = blockIdx.x * 512u + threadIdx.x;

    unsigned f4 = t & (F4 - 1);           // lane-contiguous
    unsigned p  = (t >> 7) & (PQ - 1);    // 0..1023
    unsigned b  = t >> 17;                // 0..31

    unsigned base_b = b * (L * F4);       // max 2^27, fits uint

    unsigned in0 = base_b + (2u * p) * ROW + f4;
    unsigned in1 = in0 + 2u * PQ * ROW;

    // 4 independent coalesced loads batched up front
    float4 a0 = x[in0];
    float4 a1 = x[in0 + ROW];
    float4 b0 = x[in1];
    float4 b1 = x[in1 + ROW];

    const float s = 0.70710678118654752440f;
    float4 ca0, cd0, ca1, cd1;
    ca0.x = (a0.x + a1.x) * s;  cd0.x = (a0.x - a1.x) * s;
    ca0.y = (a0.y + a1.y) * s;  cd0.y = (a0.y - a1.y) * s;
    ca0.z = (a0.z + a1.z) * s;  cd0.z = (a0.z - a1.z) * s;
    ca0.w = (a0.w + a1.w) * s;  cd0.w = (a0.w - a1.w) * s;
    ca1.x = (b0.x + b1.x) * s;  cd1.x = (b0.x - b1.x) * s;
    ca1.y = (b0.y + b1.y) * s;  cd1.y = (b0.y - b1.y) * s;
    ca1.z = (b0.z + b1.z) * s;  cd1.z = (b0.z - b1.z) * s;
    ca1.w = (b0.w + b1.w) * s;  cd1.w = (b0.w - b1.w) * s;

    unsigned outA0 = base_b + p * ROW + f4;
    unsigned outA1 = outA0 + PQ * ROW;

    out[outA0]        = ca0;
    out[outA1]        = ca1;
    out[outA0 + DOFF] = cd0;
    out[outA1 + DOFF] = cd1;
}

extern "C" void kernel_launch(void* const* d_in, const int* in_sizes, int n_in,
                              void* d_out, int out_size)
{
    const float4* x = (const float4*)d_in[0];
    float4* out = (float4*)d_out;

    haar_dwt_kernel<<<TOTAL_T / 512, 512>>>(x, out);
}